// round 17
// baseline (speedup 1.0000x reference)
#include <cuda_runtime.h>
#include <cstdint>

typedef unsigned int u32;

#define B_   256
#define L_   2048
#define E_   64
#define R_   32
#define LT_  128
#define NT_  16
#define NTHR_ 256

// ---- shared memory byte offsets ----
#define SO_STG   0                    // 128x68 f32 staging (warp-local)
#define SO_XH    34816                // 2 x 128x72 f16
#define XHB      18432
#define SO_AS    71680                // 2 x 32x136 f16
#define ASB      8704
#define SO_W1H   89088                // 64x72 f16
#define SO_W2H   98304                // 32x72 f16
#define SO_MASK  102912               // 2 x 128 f32
#define SO_DEN   103936               // 32 f32
#define SMEM_BYTES 104064

#define L2E 1.4426950408889634f

// f32-accumulator HMMA (G3 only)
__device__ __forceinline__ void mma16(float* d, u32 a0, u32 a1, u32 a2, u32 a3,
                                      u32 b0, u32 b1) {
    asm volatile("mma.sync.aligned.m16n8k16.row.col.f32.f16.f16.f32 "
                 "{%0,%1,%2,%3},{%4,%5,%6,%7},{%8,%9},{%0,%1,%2,%3};"
                 : "+f"(d[0]), "+f"(d[1]), "+f"(d[2]), "+f"(d[3])
                 : "r"(a0), "r"(a1), "r"(a2), "r"(a3), "r"(b0), "r"(b1));
}
// f16-accumulator HMMA (G1/G2)
__device__ __forceinline__ void mma16h(u32* d, u32 a0, u32 a1, u32 a2, u32 a3,
                                       u32 b0, u32 b1) {
    asm volatile("mma.sync.aligned.m16n8k16.row.col.f16.f16.f16.f16 "
                 "{%0,%1},{%2,%3,%4,%5},{%6,%7},{%0,%1};"
                 : "+r"(d[0]), "+r"(d[1])
                 : "r"(a0), "r"(a1), "r"(a2), "r"(a3), "r"(b0), "r"(b1));
}
__device__ __forceinline__ void ldsm4(u32 a, u32& r0, u32& r1, u32& r2, u32& r3) {
    asm volatile("ldmatrix.sync.aligned.m8n8.x4.shared.b16 {%0,%1,%2,%3}, [%4];"
                 : "=r"(r0), "=r"(r1), "=r"(r2), "=r"(r3) : "r"(a));
}
__device__ __forceinline__ void ldsm4t(u32 a, u32& r0, u32& r1, u32& r2, u32& r3) {
    asm volatile("ldmatrix.sync.aligned.m8n8.x4.trans.shared.b16 {%0,%1,%2,%3}, [%4];"
                 : "=r"(r0), "=r"(r1), "=r"(r2), "=r"(r3) : "r"(a));
}
__device__ __forceinline__ void stsm4t(u32 a, u32 r0, u32 r1, u32 r2, u32 r3) {
    asm volatile("stmatrix.sync.aligned.m8n8.x4.trans.shared.b16 [%0], {%1,%2,%3,%4};"
                 :: "r"(a), "r"(r0), "r"(r1), "r"(r2), "r"(r3) : "memory");
}
__device__ __forceinline__ u32 packh2(float lo, float hi) {
    u32 r; asm("cvt.rn.f16x2.f32 %0, %2, %1;" : "=r"(r) : "f"(lo), "f"(hi)); return r;
}
__device__ __forceinline__ u32 tanhh2(u32 v) {
    u32 r; asm("tanh.approx.f16x2 %0, %1;" : "=r"(r) : "r"(v)); return r;
}
__device__ __forceinline__ u32 ex2h2(u32 v) {
    u32 r; asm("ex2.approx.f16x2 %0, %1;" : "=r"(r) : "r"(v)); return r;
}
__device__ __forceinline__ u32 mulh2(u32 a, u32 b) {
    u32 r; asm("mul.rn.f16x2 %0, %1, %2;" : "=r"(r) : "r"(a), "r"(b)); return r;
}
__device__ __forceinline__ u32 addh2(u32 a, u32 b) {
    u32 r; asm("add.rn.f16x2 %0, %1, %2;" : "=r"(r) : "r"(a), "r"(b)); return r;
}
__device__ __forceinline__ float2 h22f2(u32 v) {
    float2 f;
    asm("{.reg .f16 lo, hi; mov.b32 {lo, hi}, %2; cvt.f32.f16 %0, lo; cvt.f32.f16 %1, hi;}"
        : "=f"(f.x), "=f"(f.y) : "r"(v));
    return f;
}
__device__ __forceinline__ float ldsf(u32 a) {
    float v; asm volatile("ld.shared.f32 %0, [%1];" : "=f"(v) : "r"(a)); return v;
}
__device__ __forceinline__ u32 lds32(u32 a) {
    u32 v; asm volatile("ld.shared.b32 %0, [%1];" : "=r"(v) : "r"(a)); return v;
}
__device__ __forceinline__ float4 lds128f(u32 a) {
    float4 v;
    asm volatile("ld.shared.v4.f32 {%0,%1,%2,%3}, [%4];"
                 : "=f"(v.x), "=f"(v.y), "=f"(v.z), "=f"(v.w) : "r"(a));
    return v;
}
__device__ __forceinline__ void sts64(u32 a, u32 x, u32 y) {
    asm volatile("st.shared.v2.b32 [%0], {%1,%2};" :: "r"(a), "r"(x), "r"(y) : "memory");
}
__device__ __forceinline__ void sts32(u32 a, u32 x) {
    asm volatile("st.shared.b32 [%0], %1;" :: "r"(a), "r"(x) : "memory");
}
__device__ __forceinline__ void cpa16(u32 dst, const float* src) {
    asm volatile("cp.async.cg.shared.global [%0], [%1], 16;" :: "r"(dst), "l"(src) : "memory");
}
__device__ __forceinline__ void cp_commit() { asm volatile("cp.async.commit_group;" ::: "memory"); }
__device__ __forceinline__ void cp_wait0()  { asm volatile("cp.async.wait_group 0;"  ::: "memory"); }

__global__ void __launch_bounds__(NTHR_, 2)
selfbi_h16e(const float* __restrict__ x,
            const float* __restrict__ mask,
            const float* __restrict__ W1,
            const float* __restrict__ W2,
            float* __restrict__ out)
{
    extern __shared__ char smem[];
    const u32 sb   = (u32)__cvta_generic_to_shared(smem);
    const int tid  = threadIdx.x;
    const int w    = tid >> 5;
    const int lane = tid & 31;
    const int grp  = lane >> 2;
    const int four = lane & 3;
    const int l7   = lane & 7;
    const int l8   = (lane >> 3) & 1;
    const int l16  = lane >> 4;
    const int b    = blockIdx.x;

    const float* xb = x    + (size_t)b * L_ * E_;
    const float* mb = mask + (size_t)b * L_;

    const int mt3  = w & 1;
    const int ntg3 = (w >> 1) * 2;

    // hoisted per-thread loader bases
    const int ld_row0 = w * 16 + (lane >> 4);
    const int ld_col  = (lane & 15) * 4;
    const u32 stg_ld  = sb + SO_STG + (u32)((ld_row0 * 68 + ld_col) * 4);
    const float* gsrc = xb + ld_row0 * 64 + ld_col;

    // initial tile-0 load
    {
        #pragma unroll
        for (int rep = 0; rep < 8; ++rep)
            cpa16(stg_ld + (u32)(rep * 2 * 68 * 4), gsrc + rep * 128);
        if (lane < 4)
            cpa16(sb + SO_MASK + (u32)((w * 16 + lane * 4) * 4), mb + w * 16 + lane * 4);
        cp_commit();
    }

    // weights -> f16 smem (W2 pre-scaled by log2 e)
    for (int i = tid; i < 64 * 32; i += NTHR_) {
        int d = i >> 5, e2 = (i & 31) * 2;
        sts32(sb + SO_W1H + (u32)((d * 72 + e2) * 2),
              packh2(W1[d * 64 + e2], W1[d * 64 + e2 + 1]));
    }
    for (int i = tid; i < 32 * 32; i += NTHR_) {
        int r = i >> 5, d2 = (i & 31) * 2;
        sts32(sb + SO_W2H + (u32)((r * 72 + d2) * 2),
              packh2(W2[r * 64 + d2] * L2E, W2[r * 64 + d2 + 1] * L2E));
    }
    if (tid < 32) *(float*)(smem + SO_DEN + tid * 4) = 0.0f;
    __syncthreads();

    // preload W2 B-fragments (pre-scaled)
    u32 w2f[4][4][2];
    #pragma unroll
    for (int nt = 0; nt < 4; ++nt) {
        int rn = nt * 8 + grp;
        #pragma unroll
        for (int ks = 0; ks < 4; ++ks) {
            u32 a = sb + SO_W2H + (u32)((rn * 72 + ks * 16 + four * 2) * 2);
            w2f[nt][ks][0] = lds32(a);
            w2f[nt][ks][1] = lds32(a + 16);
        }
    }

    // per-buffer base registers
    const u32 xa_b[2]  = { sb + SO_XH + (u32)(((w*16 + l7 + l8*8)*72 + l16*8)*2),
                           sb + SO_XH + XHB + (u32)(((w*16 + l7 + l8*8)*72 + l16*8)*2) };
    const u32 w1_base  =   sb + SO_W1H + (u32)(((l7 + l16*8)*72 + l8*8)*2);
    const u32 as_b[2]  = { sb + SO_AS + (u32)(((mt3*16 + l7 + l8*8)*136 + l16*8)*2),
                           sb + SO_AS + ASB + (u32)(((mt3*16 + l7 + l8*8)*136 + l16*8)*2) };
    const u32 xbm_b[2] = { sb + SO_XH + (u32)(((l7 + l8*8)*72 + ntg3*8 + l16*8)*2),
                           sb + SO_XH + XHB + (u32)(((l7 + l8*8)*72 + ntg3*8 + l16*8)*2) };
    const u32 st_b[2]  = { sb + SO_AS + (u32)(((l16*8 + l7)*136 + w*16 + l8*8)*2),
                           sb + SO_AS + ASB + (u32)(((l16*8 + l7)*136 + w*16 + l8*8)*2) };
    const int cr8 = (tid >> 4) * 8;
    const int ce0 = (tid & 15) * 4;
    const u32 stg_cv   =   sb + SO_STG + (u32)((cr8 * 68 + ce0) * 4);
    const u32 xh_cv[2] = { sb + SO_XH + (u32)((cr8 * 72 + ce0) * 2),
                           sb + SO_XH + XHB + (u32)((cr8 * 72 + ce0) * 2) };
    const int j0 = w * 16 + grp;
    const u32 mk_b[2]  = { sb + SO_MASK + (u32)(j0 * 4),
                           sb + SO_MASK + 512u + (u32)(j0 * 4) };

    float acc3a[2][4], acc3b[2][4];
    #pragma unroll
    for (int i = 0; i < 2; ++i)
        #pragma unroll
        for (int p = 0; p < 4; ++p) { acc3a[i][p] = 0.0f; acc3b[i][p] = 0.0f; }
    float denr[4][2];
    #pragma unroll
    for (int nt = 0; nt < 4; ++nt) { denr[nt][0] = 0.0f; denr[nt][1] = 0.0f; }

#define TILE_BODY(T, BUF)                                                          \
    do {                                                                           \
        /* G3(t-1): operands ready since last barrier -> run BEFORE cp wait */     \
        if ((T) > 0) {                                                             \
            _Pragma("unroll")                                                      \
            for (int ks = 0; ks < 8; ++ks) {                                       \
                u32 a0, a1, a2, a3, b0, b1, b2, b3;                                \
                ldsm4(as_b[(BUF) ^ 1] + (u32)(ks * 32), a0, a1, a2, a3);           \
                ldsm4t(xbm_b[(BUF) ^ 1] + (u32)(ks * 2304), b0, b1, b2, b3);       \
                if (ks & 1) {                                                      \
                    mma16(acc3b[0], a0, a1, a2, a3, b0, b1);                       \
                    mma16(acc3b[1], a0, a1, a2, a3, b2, b3);                       \
                } else {                                                           \
                    mma16(acc3a[0], a0, a1, a2, a3, b0, b1);                       \
                    mma16(acc3a[1], a0, a1, a2, a3, b2, b3);                       \
                }                                                                  \
            }                                                                      \
        }                                                                          \
        cp_wait0();                                                                \
        __syncwarp();                                                              \
        _Pragma("unroll")                                                          \
        for (int i = 0; i < 8; ++i) {                                              \
            float4 v = lds128f(stg_cv + (u32)(i * 68 * 4));                        \
            sts64(xh_cv[BUF] + (u32)(i * 72 * 2),                                  \
                  packh2(v.x, v.y), packh2(v.z, v.w));                             \
        }                                                                          \
        __syncwarp();                                                              \
        if ((T) + 1 < NT_) {                                                       \
            const float* s = gsrc + ((T) + 1) * (LT_ * E_);                        \
            _Pragma("unroll")                                                      \
            for (int rep = 0; rep < 8; ++rep)                                      \
                cpa16(stg_ld + (u32)(rep * 2 * 68 * 4), s + rep * 128);            \
            if (lane < 4)                                                          \
                cpa16(sb + SO_MASK + (u32)((BUF ^ 1) * 512) +                      \
                      (u32)((w * 16 + lane * 4) * 4),                              \
                      mb + ((T) + 1) * LT_ + w * 16 + lane * 4);                   \
            cp_commit();                                                           \
        }                                                                          \
        u32 acc1h[8][2];                                                           \
        _Pragma("unroll")                                                          \
        for (int n = 0; n < 8; ++n) { acc1h[n][0] = 0u; acc1h[n][1] = 0u; }        \
        _Pragma("unroll")                                                          \
        for (int ks = 0; ks < 4; ++ks) {                                           \
            u32 a0, a1, a2, a3;                                                    \
            ldsm4(xa_b[BUF] + (u32)(ks * 32), a0, a1, a2, a3);                     \
            _Pragma("unroll")                                                      \
            for (int p = 0; p < 4; ++p) {                                          \
                u32 b0, b1, b2, b3;                                                \
                ldsm4(w1_base + (u32)(p * 2304 + ks * 32), b0, b1, b2, b3);        \
                mma16h(acc1h[2 * p],     a0, a1, a2, a3, b0, b1);                  \
                mma16h(acc1h[2 * p + 1], a0, a1, a2, a3, b2, b3);                  \
            }                                                                      \
        }                                                                          \
        u32 af[4][4];                                                              \
        _Pragma("unroll")                                                          \
        for (int ks = 0; ks < 4; ++ks) {                                           \
            af[ks][0] = tanhh2(acc1h[2*ks][0]);                                    \
            af[ks][1] = tanhh2(acc1h[2*ks][1]);                                    \
            af[ks][2] = tanhh2(acc1h[2*ks+1][0]);                                  \
            af[ks][3] = tanhh2(acc1h[2*ks+1][1]);                                  \
        }                                                                          \
        u32 acc2h[4][2];                                                           \
        _Pragma("unroll")                                                          \
        for (int n = 0; n < 4; ++n) { acc2h[n][0] = 0u; acc2h[n][1] = 0u; }        \
        _Pragma("unroll")                                                          \
        for (int ks = 0; ks < 4; ++ks)                                             \
            _Pragma("unroll")                                                      \
            for (int nt = 0; nt < 4; ++nt)                                         \
                mma16h(acc2h[nt], af[ks][0], af[ks][1], af[ks][2], af[ks][3],      \
                       w2f[nt][ks][0], w2f[nt][ks][1]);                            \
        {                                                                          \
            float mk0 = ldsf(mk_b[BUF]);                                           \
            float mk1 = ldsf(mk_b[BUF] + 32);                                      \
            u32 mh0 = packh2(mk0, mk0);                                            \
            u32 mh1 = packh2(mk1, mk1);                                            \
            u32 alo[4], ahi[4];                                                    \
            _Pragma("unroll")                                                      \
            for (int nt = 0; nt < 4; ++nt) {                                       \
                alo[nt] = mulh2(ex2h2(acc2h[nt][0]), mh0);                         \
                ahi[nt] = mulh2(ex2h2(acc2h[nt][1]), mh1);                         \
            }                                                                      \
            stsm4t(st_b[BUF],                   alo[0], ahi[0], alo[1], ahi[1]);   \
            stsm4t(st_b[BUF] + (u32)(16*136*2), alo[2], ahi[2], alo[3], ahi[3]);   \
            _Pragma("unroll")                                                      \
            for (int nt = 0; nt < 4; ++nt) {                                       \
                float2 fp = h22f2(addh2(alo[nt], ahi[nt]));                        \
                denr[nt][0] += fp.x;                                               \
                denr[nt][1] += fp.y;                                               \
            }                                                                      \
        }                                                                          \
        __syncthreads();                                                           \
    } while (0)

    for (int tt = 0; tt < NT_ / 2; ++tt) {
        TILE_BODY(tt * 2,     0);
        TILE_BODY(tt * 2 + 1, 1);
    }
#undef TILE_BODY

    // ---- drain: G3 for the last tile (buf = 1) ----
    #pragma unroll
    for (int ks = 0; ks < 8; ++ks) {
        u32 a0, a1, a2, a3, b0, b1, b2, b3;
        ldsm4(as_b[1] + (u32)(ks * 32), a0, a1, a2, a3);
        ldsm4t(xbm_b[1] + (u32)(ks * 2304), b0, b1, b2, b3);
        if (ks & 1) {
            mma16(acc3b[0], a0, a1, a2, a3, b0, b1);
            mma16(acc3b[1], a0, a1, a2, a3, b2, b3);
        } else {
            mma16(acc3a[0], a0, a1, a2, a3, b0, b1);
            mma16(acc3a[1], a0, a1, a2, a3, b2, b3);
        }
    }

    // ---- den: shuffle-reduce, one atomic pass ----
    #pragma unroll
    for (int nt = 0; nt < 4; ++nt) {
        float dx = denr[nt][0], dy = denr[nt][1];
        dx += __shfl_xor_sync(0xffffffffu, dx, 4);
        dy += __shfl_xor_sync(0xffffffffu, dy, 4);
        dx += __shfl_xor_sync(0xffffffffu, dx, 8);
        dy += __shfl_xor_sync(0xffffffffu, dy, 8);
        dx += __shfl_xor_sync(0xffffffffu, dx, 16);
        dy += __shfl_xor_sync(0xffffffffu, dy, 16);
        if (grp == 0) {
            int r0 = nt * 8 + four * 2;
            atomicAdd((float*)(smem + SO_DEN + r0 * 4), dx);
            atomicAdd((float*)(smem + SO_DEN + (r0 + 1) * 4), dy);
        }
    }
    __syncthreads();

    // ---- finalize ----
    {
        int r0 = mt3 * 16 + grp, r1 = r0 + 8;
        float i0 = 1.0f / ldsf(sb + SO_DEN + (u32)(r0 * 4));
        float i1 = 1.0f / ldsf(sb + SO_DEN + (u32)(r1 * 4));
        float* ob = out + (size_t)b * R_ * E_;
        #pragma unroll
        for (int ntl = 0; ntl < 2; ++ntl) {
            int e = (ntg3 + ntl) * 8 + four * 2;
            float2 v0, v1;
            v0.x = (acc3a[ntl][0] + acc3b[ntl][0]) * i0;
            v0.y = (acc3a[ntl][1] + acc3b[ntl][1]) * i0;
            v1.x = (acc3a[ntl][2] + acc3b[ntl][2]) * i1;
            v1.y = (acc3a[ntl][3] + acc3b[ntl][3]) * i1;
            *(float2*)(ob + r0 * 64 + e) = v0;
            *(float2*)(ob + r1 * 64 + e) = v1;
        }
    }
}

extern "C" void kernel_launch(void* const* d_in, const int* in_sizes, int n_in,
                              void* d_out, int out_size)
{
    const float* x    = (const float*)d_in[0];
    const float* mask = (const float*)d_in[1];
    const float* W1   = (const float*)d_in[2];
    const float* W2   = (const float*)d_in[3];
    float* out        = (float*)d_out;

    cudaFuncSetAttribute(selfbi_h16e,
                         cudaFuncAttributeMaxDynamicSharedMemorySize, SMEM_BYTES);
    selfbi_h16e<<<B_, NTHR_, SMEM_BYTES>>>(x, mask, W1, W2, out);
}